// round 9
// baseline (speedup 1.0000x reference)
#include <cuda_runtime.h>
#include <cuda_fp16.h>
#include <cstdint>
#include <math.h>

#define N 8192
#define D 512
#define BM 128
#define NT (N / BM)                 // 64
#define NPAIRS (NT * (NT + 1) / 2)  // 2080
#define UNITS (NPAIRS * 2)          // 4160 half-tiles (128 x 64)
#define HGRID 296                   // QMMA CTAs (2 per SM)
#define FGRID 148                   // HFMA2 CTAs (1 per SM)

// H path: fp8 tiles, K-chunks of 128 (128B rows), 3 stages
#define BKC 128
#define NCH_H (D / BKC)             // 4
#define TILE_A 16384                // 128 x 128B
#define TILE_B 8192                 // 64 x 128B
#define STAGE_BYTES (TILE_A + TILE_B)
#define SMEM_BYTES (1024 + 3 * STAGE_BYTES)   // 74752

// F path: fp16, K-chunks of 64 (32 half2), double buffer (reuses same smem)
#define AST 132                     // half2 row stride, A (128 rows + pad)
#define BST 68                      // half2 row stride, B (64 rows + pad)

__device__ __half  g_nrm[N * D];    // fp16 normalized rows (F path)
__device__ uint8_t g_q[N * D];      // e4m3 quantized rows  (H path)
__device__ float   g_scale[N];
__device__ double  g_accum;
__device__ unsigned g_ctr;          // lo pops | hi pops << 16

// ---------------------------------------------------------------------------
// PTX helpers (arch-agnostic)
// ---------------------------------------------------------------------------
__device__ __forceinline__ uint32_t smem_u32(const void* p) {
    uint32_t a;
    asm("{ .reg .u64 t; cvta.to.shared.u64 t, %1; cvt.u32.u64 %0, t; }" : "=r"(a) : "l"(p));
    return a;
}
__device__ __forceinline__ void cp16(uint32_t saddr, const void* g) {
    asm volatile("cp.async.cg.shared.global [%0], [%1], 16;" :: "r"(saddr), "l"(g) : "memory");
}
__device__ __forceinline__ void cp_commit() {
    asm volatile("cp.async.commit_group;" ::: "memory");
}
template <int NN>
__device__ __forceinline__ void cp_wait() {
    asm volatile("cp.async.wait_group %0;" :: "n"(NN) : "memory");
}
__device__ __forceinline__ void ldsm_x4(uint32_t* r, uint32_t addr) {
    asm volatile("ldmatrix.sync.aligned.m8n8.x4.shared.b16 {%0,%1,%2,%3}, [%4];"
                 : "=r"(r[0]), "=r"(r[1]), "=r"(r[2]), "=r"(r[3]) : "r"(addr));
}
__device__ __forceinline__ void qmma16832(float* d, const uint32_t* a,
                                          uint32_t b0, uint32_t b1) {
    asm volatile(
        "mma.sync.aligned.m16n8k32.row.col.f32.e4m3.e4m3.f32 "
        "{%0,%1,%2,%3}, {%4,%5,%6,%7}, {%8,%9}, {%0,%1,%2,%3};"
        : "+f"(d[0]), "+f"(d[1]), "+f"(d[2]), "+f"(d[3])
        : "r"(a[0]), "r"(a[1]), "r"(a[2]), "r"(a[3]), "r"(b0), "r"(b1));
}
__device__ __forceinline__ uint32_t cvt_e4m3x2(float hi, float lo) {
    uint16_t h;
    asm("cvt.rn.satfinite.e4m3x2.f32 %0, %1, %2;" : "=h"(h) : "f"(hi), "f"(lo));
    return (uint32_t)h;
}
__device__ __forceinline__ void decode_tile(int b, int& bi, int& bj) {
    int j = (int)((sqrtf(8.0f * (float)b + 1.0f) - 1.0f) * 0.5f);
    while ((j + 1) * (j + 2) / 2 <= b) j++;
    while (j * (j + 1) / 2 > b) j--;
    bi = b - j * (j + 1) / 2;
    bj = j;
}

// ---------------------------------------------------------------------------
// Kernel 1: normalize + emit fp16 copy, e4m3 copy, per-row scale.
// ---------------------------------------------------------------------------
__global__ __launch_bounds__(256) void quantize_kernel(const float* __restrict__ in) {
    int row  = blockIdx.x * 8 + (threadIdx.x >> 5);
    int lane = threadIdx.x & 31;
    if (blockIdx.x == 0 && threadIdx.x == 0) { g_accum = 0.0; g_ctr = 0u; }

    const float4* src = (const float4*)(in + (size_t)row * D);
    float4 v[4];
    float ss = 0.0f;
    #pragma unroll
    for (int i = 0; i < 4; i++) {
        v[i] = src[i * 32 + lane];
        ss += v[i].x * v[i].x + v[i].y * v[i].y + v[i].z * v[i].z + v[i].w * v[i].w;
    }
    #pragma unroll
    for (int o = 16; o; o >>= 1) ss += __shfl_xor_sync(0xffffffffu, ss, o);
    float inv = rsqrtf(ss);

    float amax = 0.0f;
    #pragma unroll
    for (int i = 0; i < 4; i++)
        amax = fmaxf(amax, fmaxf(fmaxf(fabsf(v[i].x), fabsf(v[i].y)),
                                 fmaxf(fabsf(v[i].z), fabsf(v[i].w))));
    amax *= inv;
    #pragma unroll
    for (int o = 16; o; o >>= 1) amax = fmaxf(amax, __shfl_xor_sync(0xffffffffu, amax, o));

    float s    = amax * (1.0f / 448.0f);
    float qmul = inv * (448.0f / amax);
    if (lane == 0) g_scale[row] = s;

    uint2* dn = (uint2*)(g_nrm + (size_t)row * D);
    uint32_t* dq = (uint32_t*)(g_q + (size_t)row * D);
    #pragma unroll
    for (int i = 0; i < 4; i++) {
        __half2 lo = __floats2half2_rn(v[i].x * inv, v[i].y * inv);
        __half2 hi = __floats2half2_rn(v[i].z * inv, v[i].w * inv);
        uint2 o2;
        o2.x = *(uint32_t*)&lo;
        o2.y = *(uint32_t*)&hi;
        dn[i * 32 + lane] = o2;

        uint32_t l16 = cvt_e4m3x2(v[i].y * qmul, v[i].x * qmul);
        uint32_t h16 = cvt_e4m3x2(v[i].w * qmul, v[i].z * qmul);
        dq[i * 32 + lane] = l16 | (h16 << 16);
    }
}

// ---------------------------------------------------------------------------
// Kernel 2: hybrid gram over 4160 half-tiles (128 rows x 64 cols).
//   bid < 296 : QMMA path (tensor pipe), pops units from LOW end
//   bid >= 296: HFMA2 path (fma pipe),   pops units from HIGH end
// Classic placement maps bids {x, x+148, x+296} to the same SM -> 2 H + 1 F.
// ---------------------------------------------------------------------------
extern __shared__ char dynsmem[];

__global__ __launch_bounds__(256, 3) void gram_hybrid_kernel() {
    const bool isF = (blockIdx.x >= HGRID);
    int t    = threadIdx.x;
    int wid  = t >> 5;
    int lane = t & 31;

    uint32_t smem0 = smem_u32(dynsmem);
    uint32_t base  = (smem0 + 1023) & ~1023u;
    char* basep = dynsmem + (base - smem0);

    __shared__ int   s_unit;
    __shared__ float red[8];
    __shared__ float sScale[192];   // [0..127]=A rows, [128..191]=B half rows

    float local = 0.0f;

    // H addressing
    int warp_m = wid & 1;       // 2 warps over M (64 rows each)
    int warp_n = wid >> 1;      // 4 warps over N (16 cols each)
    int a_row  = warp_m * 64 + (lane & 15);
    int a_kh   = lane >> 4;
    int b_row  = warp_n * 16 + (lane & 7) + (((lane >> 3) & 1) << 3);
    uint32_t sA[3], sB[3];
    #pragma unroll
    for (int s = 0; s < 3; s++) {
        sA[s] = base + s * STAGE_BYTES;
        sB[s] = sA[s] + TILE_A;
    }

    // F addressing
    half2* As2 = (half2*)basep;                       // [2][32*AST]
    half2* Bs2 = (half2*)(basep + 2 * 32 * AST * 4);  // [2][32*BST]
    int tx = t & 15;
    int ty = t >> 4;

    for (;;) {
        __syncthreads();
        if (t == 0) {
            unsigned old = atomicAdd(&g_ctr, isF ? 0x10000u : 1u);
            unsigned lo = old & 0xffffu, hi = old >> 16;
            s_unit = (lo + hi < (unsigned)UNITS)
                         ? (isF ? (UNITS - 1 - (int)hi) : (int)lo)
                         : -1;
        }
        __syncthreads();
        int unit = s_unit;
        if (unit < 0) break;

        int tile = unit >> 1, half = unit & 1;
        int bi, bj;
        decode_tile(tile, bi, bj);
        const bool diag = (bi == bj);
        int brow0 = bj * BM + half * 64;   // global first B row

        if (!isF) {
            // ====================== QMMA half-tile ======================
            if (t < 128)       sScale[t] = g_scale[bi * BM + t];
            else if (t < 192)  sScale[t] = g_scale[brow0 + (t - 128)];

            const uint8_t* __restrict__ gA = g_q + (size_t)bi * BM * D;
            const uint8_t* __restrict__ gB = g_q + (size_t)brow0 * D;

            auto loadA = [&](uint32_t s, int k0) {
                int row = t >> 1;
                const char* gp = (const char*)(gA + (size_t)row * D + k0);
                uint32_t srow = s + (uint32_t)row * 128;
                #pragma unroll
                for (int i = 0; i < 4; i++) {
                    int c = (t & 1) * 4 + i;
                    cp16(srow + (((uint32_t)c ^ (row & 7)) << 4), gp + c * 16);
                }
            };
            auto loadB = [&](uint32_t s, int k0) {
                int row = t >> 2;
                const char* gp = (const char*)(gB + (size_t)row * D + k0);
                uint32_t srow = s + (uint32_t)row * 128;
                #pragma unroll
                for (int i = 0; i < 2; i++) {
                    int c = (t & 3) * 2 + i;
                    cp16(srow + (((uint32_t)c ^ (row & 7)) << 4), gp + c * 16);
                }
            };

            float acc[4][2][4];
            #pragma unroll
            for (int mi = 0; mi < 4; mi++)
                #pragma unroll
                for (int nj = 0; nj < 2; nj++)
                    #pragma unroll
                    for (int r = 0; r < 4; r++) acc[mi][nj][r] = 0.0f;

            loadA(sA[0], 0);   loadB(sB[0], 0);   cp_commit();
            loadA(sA[1], BKC); loadB(sB[1], BKC); cp_commit();

            for (int c = 0; c < NCH_H; c++) {
                if (c < NCH_H - 1) cp_wait<1>(); else cp_wait<0>();
                __syncthreads();
                if (c + 2 < NCH_H) {
                    loadA(sA[(c + 2) % 3], (c + 2) * BKC);
                    loadB(sB[(c + 2) % 3], (c + 2) * BKC);
                    cp_commit();
                }
                uint32_t ab = sA[c % 3], bb = sB[c % 3];
                #pragma unroll
                for (int kk = 0; kk < 4; kk++) {
                    uint32_t Af[4][4], Bf[4];
                    int kchunk = kk * 2 + a_kh;
                    #pragma unroll
                    for (int mi = 0; mi < 4; mi++) {
                        int r = a_row + mi * 16;
                        ldsm_x4(Af[mi], ab + (uint32_t)r * 128 +
                                        (((uint32_t)kchunk ^ (r & 7)) << 4));
                    }
                    ldsm_x4(Bf, bb + (uint32_t)b_row * 128 +
                                (((uint32_t)kchunk ^ (b_row & 7)) << 4));
                    #pragma unroll
                    for (int mi = 0; mi < 4; mi++)
                        #pragma unroll
                        for (int nj = 0; nj < 2; nj++)
                            qmma16832(acc[mi][nj], Af[mi], Bf[nj], Bf[nj + 2]);
                }
            }

            int lrow0 = warp_m * 64 + (lane >> 2);
            int lcol0 = warp_n * 16 + (lane & 3) * 2;
            #pragma unroll
            for (int mi = 0; mi < 4; mi++)
                #pragma unroll
                for (int nj = 0; nj < 2; nj++)
                    #pragma unroll
                    for (int r = 0; r < 4; r++) {
                        int h  = r >> 1, bc = r & 1;
                        int im = lrow0 + mi * 16 + h * 8;
                        int jl = lcol0 + nj * 8 + bc;         // 0..63 in half
                        float d = acc[mi][nj][r];
                        bool ok = diag ? (im < half * 64 + jl) : true;
                        if (ok && d > 0.0f)
                            local += d * sScale[im] * sScale[128 + jl];
                    }
        } else {
            // ====================== HFMA2 half-tile ======================
            const __half* __restrict__ fA = g_nrm + (size_t)bi * BM * D;
            const __half* __restrict__ fB = g_nrm + (size_t)brow0 * D;

            auto fload = [&](int buf, int k0) {
                // A: 128 rows x 32 k2 -> [k2][row]
                int r  = t >> 1;
                int kb = (t & 1) * 16;
                const uint4* src = (const uint4*)(fA + (size_t)r * D + k0 + kb * 2);
                half2* dst = As2 + buf * 32 * AST;
                #pragma unroll
                for (int i = 0; i < 4; i++) {
                    uint4 v = src[i];
                    uint32_t* c0 = (uint32_t*)(dst + (kb + i * 4) * AST + r);
                    c0[0 * AST] = v.x; c0[1 * AST] = v.y;
                    c0[2 * AST] = v.z; c0[3 * AST] = v.w;
                }
                // B: 64 rows x 32 k2
                int rb  = t >> 2;
                int kbb = (t & 3) * 8;
                const uint4* srcb = (const uint4*)(fB + (size_t)rb * D + k0 + kbb * 2);
                half2* dstb = Bs2 + buf * 32 * BST;
                #pragma unroll
                for (int i = 0; i < 2; i++) {
                    uint4 v = srcb[i];
                    uint32_t* c0 = (uint32_t*)(dstb + (kbb + i * 4) * BST + rb);
                    c0[0 * BST] = v.x; c0[1 * BST] = v.y;
                    c0[2 * BST] = v.z; c0[3 * BST] = v.w;
                }
            };

            half2 c2[8][4];
            #pragma unroll
            for (int i = 0; i < 8; i++)
                #pragma unroll
                for (int j = 0; j < 4; j++) c2[i][j] = __float2half2_rn(0.0f);

            fload(0, 0);
            __syncthreads();
            for (int c = 0; c < 8; c++) {
                if (c + 1 < 8) fload((c + 1) & 1, (c + 1) * 64);
                half2* Ab = As2 + (c & 1) * 32 * AST;
                half2* Bb = Bs2 + (c & 1) * 32 * BST;
                #pragma unroll 4
                for (int k2 = 0; k2 < 32; k2++) {
                    half2 a2[8], b2[4];
                    *(uint4*)&a2[0] = *(uint4*)(Ab + k2 * AST + ty * 4);
                    *(uint4*)&a2[4] = *(uint4*)(Ab + k2 * AST + 64 + ty * 4);
                    *(uint4*)&b2[0] = *(uint4*)(Bb + k2 * BST + tx * 4);
                    #pragma unroll
                    for (int i = 0; i < 8; i++)
                        #pragma unroll
                        for (int j = 0; j < 4; j++)
                            c2[i][j] = __hfma2(a2[i], b2[j], c2[i][j]);
                }
                __syncthreads();
            }

            #pragma unroll
            for (int i = 0; i < 8; i++) {
                int li = (i < 4) ? (ty * 4 + i) : (64 + ty * 4 + i - 4);
                #pragma unroll
                for (int j = 0; j < 4; j++) {
                    int jl = tx * 4 + j;
                    float v = __low2float(c2[i][j]) + __high2float(c2[i][j]);
                    bool ok = diag ? (li < half * 64 + jl) : true;
                    if (ok && v > 0.0f) local += v;
                }
            }
        }
    }

    #pragma unroll
    for (int o = 16; o; o >>= 1) local += __shfl_xor_sync(0xffffffffu, local, o);
    if (lane == 0) red[wid] = local;
    __syncthreads();
    if (t == 0) {
        float s = 0.0f;
        #pragma unroll
        for (int w = 0; w < 8; w++) s += red[w];
        atomicAdd(&g_accum, (double)s);
    }
}

// ---------------------------------------------------------------------------
// Kernel 3: finalize.
// ---------------------------------------------------------------------------
__global__ void finalize_kernel(float* __restrict__ out, int out_size) {
    double v = 2.0 * g_accum / ((double)N * (double)N);
    float f = (float)v;
    out[0] = f;
    if (out_size > 1) out[1] = f;
}

extern "C" void kernel_launch(void* const* d_in, const int* in_sizes, int n_in,
                              void* d_out, int out_size) {
    const float* id = (const float*)d_in[0];
    cudaFuncSetAttribute(gram_hybrid_kernel, cudaFuncAttributeMaxDynamicSharedMemorySize,
                         SMEM_BYTES);
    quantize_kernel<<<N / 8, 256>>>(id);
    gram_hybrid_kernel<<<HGRID + FGRID, 256, SMEM_BYTES>>>();
    finalize_kernel<<<1, 1>>>((float*)d_out, out_size);
}

// round 10
// speedup vs baseline: 1.3769x; 1.3769x over previous
#include <cuda_runtime.h>
#include <cstdint>
#include <math.h>

#define N 8192
#define D 512
#define BM 128
#define NT (N / BM)                 // 64
#define NPAIRS (NT * (NT + 1) / 2)  // 2080
#define BKC 128                     // fp8 K elements per chunk (128B rows)
#define NCHUNKS (D / BKC)           // 4
#define NSTAGE 3
#define TILE_BYTES (BM * BKC)       // 16384
#define SMEM_BYTES (1024 + 2 * NSTAGE * TILE_BYTES)

__device__ uint8_t  g_q[N * D];     // e4m3-quantized unit rows
__device__ float    g_scale[N];     // per-row quant scale
__device__ double   g_accum;        // zero-init; reset by last CTA each run
__device__ unsigned g_done;
__device__ unsigned g_flag[NT];     // per-128-row-block ready flags

// ---------------------------------------------------------------------------
// PTX helpers (arch-agnostic)
// ---------------------------------------------------------------------------
__device__ __forceinline__ uint32_t smem_u32(const void* p) {
    uint32_t a;
    asm("{ .reg .u64 t; cvta.to.shared.u64 t, %1; cvt.u32.u64 %0, t; }" : "=r"(a) : "l"(p));
    return a;
}
__device__ __forceinline__ void cp16(uint32_t saddr, const void* g) {
    asm volatile("cp.async.cg.shared.global [%0], [%1], 16;" :: "r"(saddr), "l"(g) : "memory");
}
__device__ __forceinline__ void cp_commit() {
    asm volatile("cp.async.commit_group;" ::: "memory");
}
template <int NN>
__device__ __forceinline__ void cp_wait() {
    asm volatile("cp.async.wait_group %0;" :: "n"(NN) : "memory");
}
__device__ __forceinline__ void ldsm_x4(uint32_t* r, uint32_t addr) {
    asm volatile("ldmatrix.sync.aligned.m8n8.x4.shared.b16 {%0,%1,%2,%3}, [%4];"
                 : "=r"(r[0]), "=r"(r[1]), "=r"(r[2]), "=r"(r[3]) : "r"(addr));
}
__device__ __forceinline__ void qmma16832(float* d, const uint32_t* a,
                                          uint32_t b0, uint32_t b1) {
    asm volatile(
        "mma.sync.aligned.m16n8k32.row.col.f32.e4m3.e4m3.f32 "
        "{%0,%1,%2,%3}, {%4,%5,%6,%7}, {%8,%9}, {%0,%1,%2,%3};"
        : "+f"(d[0]), "+f"(d[1]), "+f"(d[2]), "+f"(d[3])
        : "r"(a[0]), "r"(a[1]), "r"(a[2]), "r"(a[3]), "r"(b0), "r"(b1));
}
__device__ __forceinline__ uint32_t cvt_e4m3x2(float hi, float lo) {
    uint16_t h;
    asm("cvt.rn.satfinite.e4m3x2.f32 %0, %1, %2;" : "=h"(h) : "f"(hi), "f"(lo));
    return (uint32_t)h;
}

// ---------------------------------------------------------------------------
// Fused kernel.
//   bid < 64 : quantize rows [bid*128, bid*128+128), publish flag.
//   bid >= 64: QMMA 128x128 upper-triangle Gram tile (bid-64), after
//              spinning on its two source-block flags.
// Last finishing tile CTA writes the output and resets device state so the
// next graph replay starts clean.
// ---------------------------------------------------------------------------
extern __shared__ char dynsmem[];

__global__ __launch_bounds__(256, 2) void fused_kernel(const float* __restrict__ in,
                                                       float* __restrict__ out,
                                                       int out_size) {
    int t    = threadIdx.x;
    int wid  = t >> 5;
    int lane = t & 31;

    if (blockIdx.x < NT) {
        // ===================== quantizer CTA =====================
        int blk = blockIdx.x;
        #pragma unroll 1
        for (int i = 0; i < 16; i++) {
            int row = blk * BM + wid * 16 + i;
            const float4* src = (const float4*)(in + (size_t)row * D);
            float4 v[4];
            float ss = 0.0f;
            #pragma unroll
            for (int q = 0; q < 4; q++) {
                v[q] = src[q * 32 + lane];
                ss += v[q].x * v[q].x + v[q].y * v[q].y + v[q].z * v[q].z + v[q].w * v[q].w;
            }
            #pragma unroll
            for (int o = 16; o; o >>= 1) ss += __shfl_xor_sync(0xffffffffu, ss, o);
            float inv = rsqrtf(ss);

            float amax = 0.0f;
            #pragma unroll
            for (int q = 0; q < 4; q++)
                amax = fmaxf(amax, fmaxf(fmaxf(fabsf(v[q].x), fabsf(v[q].y)),
                                         fmaxf(fabsf(v[q].z), fabsf(v[q].w))));
            amax *= inv;
            #pragma unroll
            for (int o = 16; o; o >>= 1)
                amax = fmaxf(amax, __shfl_xor_sync(0xffffffffu, amax, o));

            float s    = amax * (1.0f / 448.0f);
            float qmul = inv * (448.0f / amax);
            if (lane == 0) g_scale[row] = s;

            uint32_t* dq = (uint32_t*)(g_q + (size_t)row * D);
            #pragma unroll
            for (int q = 0; q < 4; q++) {
                uint32_t l16 = cvt_e4m3x2(v[q].y * qmul, v[q].x * qmul);
                uint32_t h16 = cvt_e4m3x2(v[q].w * qmul, v[q].z * qmul);
                dq[q * 32 + lane] = l16 | (h16 << 16);
            }
        }
        __threadfence();
        __syncthreads();
        if (t == 0) atomicExch(&g_flag[blk], 1u);
        return;
    }

    // ======================== QMMA tile CTA ========================
    int b = blockIdx.x - NT;
    int bj = (int)((sqrtf(8.0f * (float)b + 1.0f) - 1.0f) * 0.5f);
    while ((bj + 1) * (bj + 2) / 2 <= b) bj++;
    while (bj * (bj + 1) / 2 > b) bj--;
    int bi = b - bj * (bj + 1) / 2;

    // wait for source blocks to be quantized
    if (t == 0) {
        while (atomicAdd(&g_flag[bi], 0u) == 0u) __nanosleep(128);
        while (atomicAdd(&g_flag[bj], 0u) == 0u) __nanosleep(128);
    }
    __syncthreads();
    __threadfence();

    const uint8_t* __restrict__ gA = g_q + (size_t)bi * BM * D;
    const uint8_t* __restrict__ gB = g_q + (size_t)bj * BM * D;
    const bool diag = (bi == bj);

    int warp_m = wid & 1;    // 2 warps over M (64 each)
    int warp_n = wid >> 1;   // 4 warps over N (32 each)

    __shared__ float sScale[256];
    if (t < 128) sScale[t] = g_scale[bi * BM + t];
    else         sScale[t] = g_scale[bj * BM + (t - 128)];

    uint32_t smem0 = smem_u32(dynsmem);
    uint32_t base  = (smem0 + 1023) & ~1023u;
    uint32_t sA[NSTAGE], sB[NSTAGE];
    #pragma unroll
    for (int s = 0; s < NSTAGE; s++) {
        sA[s] = base + (2 * s)     * TILE_BYTES;
        sB[s] = base + (2 * s + 1) * TILE_BYTES;
    }

    auto load_tile = [&](const uint8_t* __restrict__ g, uint32_t s, int k0) {
        int row = t >> 1;
        const char* gp = (const char*)(g + (size_t)row * D + k0);
        uint32_t srow = s + (uint32_t)row * 128;
        #pragma unroll
        for (int i = 0; i < 4; i++) {
            int c = (t & 1) * 4 + i;
            cp16(srow + (((uint32_t)c ^ (row & 7)) << 4), gp + c * 16);
        }
    };

    float acc[4][4][4];
    #pragma unroll
    for (int mi = 0; mi < 4; mi++)
        #pragma unroll
        for (int nj = 0; nj < 4; nj++)
            #pragma unroll
            for (int r = 0; r < 4; r++) acc[mi][nj][r] = 0.0f;

    load_tile(gA, sA[0], 0);
    load_tile(gB, sB[0], 0);
    cp_commit();
    load_tile(gA, sA[1], BKC);
    load_tile(gB, sB[1], BKC);
    cp_commit();

    int a_row = warp_m * 64 + (lane & 15);
    int a_kh  = lane >> 4;
    int b_row = warp_n * 32 + (lane & 7) + (((lane >> 3) & 1) << 3);

    for (int c = 0; c < NCHUNKS; c++) {
        if (c < NCHUNKS - 1) cp_wait<1>(); else cp_wait<0>();
        __syncthreads();

        if (c + 2 < NCHUNKS) {
            load_tile(gA, sA[(c + 2) % NSTAGE], (c + 2) * BKC);
            load_tile(gB, sB[(c + 2) % NSTAGE], (c + 2) * BKC);
            cp_commit();
        }

        uint32_t a_base = sA[c % NSTAGE], b_base = sB[c % NSTAGE];
        #pragma unroll
        for (int kk = 0; kk < 4; kk++) {
            uint32_t Af[4][4], Bf[2][4];
            int kchunk = kk * 2 + a_kh;
            #pragma unroll
            for (int mi = 0; mi < 4; mi++) {
                int r = a_row + mi * 16;
                ldsm_x4(Af[mi], a_base + (uint32_t)r * 128 +
                                (((uint32_t)kchunk ^ (r & 7)) << 4));
            }
            #pragma unroll
            for (int p = 0; p < 2; p++) {
                int r = b_row + p * 16;
                ldsm_x4(Bf[p], b_base + (uint32_t)r * 128 +
                               (((uint32_t)kchunk ^ (r & 7)) << 4));
            }
            #pragma unroll
            for (int mi = 0; mi < 4; mi++)
                #pragma unroll
                for (int nj = 0; nj < 4; nj++)
                    qmma16832(acc[mi][nj], Af[mi],
                              Bf[nj >> 1][nj & 1], Bf[nj >> 1][(nj & 1) + 2]);
        }
    }

    // Epilogue: scale, relu, strict-upper mask on diagonal tiles.
    int lrow0 = warp_m * 64 + (lane >> 2);
    int lcol0 = warp_n * 32 + (lane & 3) * 2;

    float si[4][2], sj[4][2];
    #pragma unroll
    for (int mi = 0; mi < 4; mi++)
        #pragma unroll
        for (int h = 0; h < 2; h++)
            si[mi][h] = sScale[lrow0 + mi * 16 + h * 8];
    #pragma unroll
    for (int nj = 0; nj < 4; nj++)
        #pragma unroll
        for (int bc = 0; bc < 2; bc++)
            sj[nj][bc] = sScale[128 + lcol0 + nj * 8 + bc];

    float local = 0.0f;
    #pragma unroll
    for (int mi = 0; mi < 4; mi++)
        #pragma unroll
        for (int nj = 0; nj < 4; nj++)
            #pragma unroll
            for (int r = 0; r < 4; r++) {
                int h  = r >> 1, bc = r & 1;
                int im = lrow0 + mi * 16 + h * 8;
                int jn = lcol0 + nj * 8 + bc;
                float d = acc[mi][nj][r];
                bool ok = diag ? (im < jn) : true;
                if (ok && d > 0.0f) local += d * si[mi][h] * sj[nj][bc];
            }

    #pragma unroll
    for (int o = 16; o; o >>= 1) local += __shfl_xor_sync(0xffffffffu, local, o);
    __shared__ float red[8];
    if (lane == 0) red[wid] = local;
    __syncthreads();

    if (t == 0) {
        float s = 0.0f;
        #pragma unroll
        for (int w = 0; w < 8; w++) s += red[w];
        atomicAdd(&g_accum, (double)s);
        __threadfence();
        unsigned d = atomicAdd(&g_done, 1u);
        if (d == (unsigned)(NPAIRS - 1)) {
            // all tile CTAs have accumulated (each fenced before its g_done add)
            __threadfence();
            double v = 2.0 * g_accum / ((double)N * (double)N);
            float f = (float)v;
            out[0] = f;
            if (out_size > 1) out[1] = f;
            // reset device state for the next graph replay
            g_accum = 0.0;
            g_done  = 0u;
            #pragma unroll
            for (int i = 0; i < NT; i++) g_flag[i] = 0u;
            __threadfence();
        }
    }
}

extern "C" void kernel_launch(void* const* d_in, const int* in_sizes, int n_in,
                              void* d_out, int out_size) {
    const float* id = (const float*)d_in[0];
    cudaFuncSetAttribute(fused_kernel, cudaFuncAttributeMaxDynamicSharedMemorySize,
                         SMEM_BYTES);
    fused_kernel<<<NT + NPAIRS, 256, SMEM_BYTES>>>(id, (float*)d_out, out_size);
}